// round 1
// baseline (speedup 1.0000x reference)
#include <cuda_runtime.h>
#include <math.h>

#define BN 128
#define LN 2048
#define FN 128
#define HN 256
#define G3 768
#define NTICK 5
#define TMX (LN + NTICK)
#define NC 128
#define NTH 256

// Scratch (module-scope device memory; no runtime allocation)
__device__ float d_Hbuf[2][HN * BN];   // ping-pong h, layout: ((k>>2)*BN + s)*4 + (k&3)
__device__ float d_Hfinal[BN * HN];    // final h per ORIGINAL batch index, row-major [b][j]
__device__ int d_perm[BN];             // sorted (desc by len) slot -> original batch
__device__ int d_slen[BN];             // sorted lens
__device__ int d_ns[TMX];              // #batches with len > t (in-seq count)
__device__ int d_maxT;
__device__ unsigned d_ctr;             // global barrier counter

// ---------------- setup: sort batches, reset state (every launch) ----------------
__global__ __launch_bounds__(NTH) void setup_kernel(const int* __restrict__ lens) {
    __shared__ int sl[BN];
    int tid = threadIdx.x;
    if (tid < BN) sl[tid] = lens[tid];
    __syncthreads();
    if (tid < BN) {
        int ml = sl[tid];
        int r = 0;
        for (int i = 0; i < BN; i++) {
            int li = sl[i];
            if (li > ml || (li == ml && i < tid)) r++;
        }
        d_perm[r] = tid;
        d_slen[r] = ml;
    }
    if (tid == 0) {
        int mx = 0;
        for (int i = 0; i < BN; i++) mx = (sl[i] > mx) ? sl[i] : mx;
        d_maxT = mx + NTICK;
        d_ctr = 0u;
    }
    for (int t = tid; t < TMX; t += NTH) {
        int c = 0;
        for (int i = 0; i < BN; i++) c += (sl[i] > t) ? 1 : 0;
        d_ns[t] = c;
    }
    float* hb = &d_Hbuf[0][0];
    for (int i = tid; i < 2 * HN * BN; i += NTH) hb[i] = 0.f;
}

// ---------------- activations (fast, ~1e-7 abs err) ----------------
__device__ __forceinline__ float fclamp15(float v) {
    return fminf(fmaxf(v, -15.f), 15.f);
}
__device__ __forceinline__ float ftanh(float v) {
    float e = __expf(2.f * fclamp15(v));
    return __fdividef(e - 1.f, e + 1.f);
}
__device__ __forceinline__ float fsig(float v) {
    return __fdividef(1.f, 1.f + __expf(-fclamp15(v)));
}

// ---------------- main persistent lockstep LSTM ----------------
// grid = 128 CTAs (co-resident), 256 threads: thread = (s = tid&127 batch slot, d = tid>>7 hidden dim)
// CTA bx owns hidden dims j = 2*bx + d (d=0,1) -> pre columns {j, 256+j, 512+j}
__global__ __launch_bounds__(NTH, 1) void lstm_kernel(
    const float* __restrict__ x, const float* __restrict__ W,
    const float* __restrict__ R, const float* __restrict__ b,
    const float* __restrict__ bt)
{
    extern __shared__ float sm[];
    float* Rs = sm;                       // [HN][2][4] = 2048 floats (g padded to 4)
    float* Ws = sm + 2048;                // [FN][2][4] = 1024 floats
    float* xs = sm + 3072;                // [FN][129]  = 16512 floats (pad row to 129 -> conflict-free)
    int* sperm = (int*)(sm + 19584);      // [BN]
    int* slen  = sperm + BN;              // [BN]

    const int tid = threadIdx.x;
    const int bx  = blockIdx.x;
    const int s   = tid & (BN - 1);
    const int d   = tid >> 7;
    const int j   = (bx << 1) + d;

    // load weight slices
    for (int i = tid; i < HN * 6; i += NTH) {
        int k = i / 6, rem = i % 6, dd = rem / 3, g = rem % 3;
        Rs[(k * 2 + dd) * 4 + g] = R[k * G3 + g * HN + ((bx << 1) + dd)];
    }
    for (int i = tid; i < FN * 6; i += NTH) {
        int k = i / 6, rem = i % 6, dd = rem / 3, g = rem % 3;
        Ws[(k * 2 + dd) * 4 + g] = W[k * G3 + g * HN + ((bx << 1) + dd)];
    }
    if (tid < BN) { sperm[tid] = d_perm[tid]; slen[tid] = d_slen[tid]; }
    __syncthreads();

    const int mylen = slen[s];
    const int myb   = sperm[s];
    const int myT   = mylen + NTICK;
    const float b0 = b[j], b1 = b[j + HN], b2 = b[j + 2 * HN];
    const float k0t = bt[j], k1t = bt[j + HN], k2t = bt[j + 2 * HN];
    const int maxT = d_maxT;

    const float4* Rs4 = (const float4*)Rs;
    const float4* Ws4 = (const float4*)Ws;

    float c = 0.f, h = 0.f;

    for (int t = 0; t < maxT; t++) {
        const int p = t & 1;
        const float4* hp4 = (const float4*)(&d_Hbuf[p][0]);
        float* hnext = &d_Hbuf[p ^ 1][0];

        // stage x_t rows for in-seq batches (prefix of sorted order)
        const int ns = (t < LN) ? __ldg(&d_ns[t]) : 0;
        for (int idx = tid; idx < (ns << 7); idx += NTH) {
            int s2 = idx >> 7;
            int kk = idx & (FN - 1);
            xs[kk * 129 + s2] = __ldg(&x[((size_t)sperm[s2] * LN + t) * FN + kk]);
        }
        __syncthreads();

        if (t < myT) {
            float a0 = b0, a1 = b1, a2 = b2;
            const bool inseq = (t < mylen);
            if (!inseq) { a0 += k0t; a1 += k1t; a2 += k2t; }
            if (inseq) {
                #pragma unroll 4
                for (int kk = 0; kk < FN; kk++) {
                    float xv = xs[kk * 129 + s];
                    float4 w4 = Ws4[kk * 2 + d];
                    a0 = fmaf(xv, w4.x, a0);
                    a1 = fmaf(xv, w4.y, a1);
                    a2 = fmaf(xv, w4.z, a2);
                }
            }
            // recurrent part: h_prev (L2-coherent via .cg) x R slice (smem)
            #pragma unroll 4
            for (int g = 0; g < HN / 4; g++) {
                float4 h4 = __ldcg(hp4 + (g << 7) + s);
                int kb = g << 2;
                float4 r0 = Rs4[(kb + 0) * 2 + d];
                float4 r1 = Rs4[(kb + 1) * 2 + d];
                float4 r2 = Rs4[(kb + 2) * 2 + d];
                float4 r3 = Rs4[(kb + 3) * 2 + d];
                a0 = fmaf(h4.x, r0.x, a0); a0 = fmaf(h4.y, r1.x, a0);
                a0 = fmaf(h4.z, r2.x, a0); a0 = fmaf(h4.w, r3.x, a0);
                a1 = fmaf(h4.x, r0.y, a1); a1 = fmaf(h4.y, r1.y, a1);
                a1 = fmaf(h4.z, r2.y, a1); a1 = fmaf(h4.w, r3.y, a1);
                a2 = fmaf(h4.x, r0.z, a2); a2 = fmaf(h4.y, r1.z, a2);
                a2 = fmaf(h4.z, r2.z, a2); a2 = fmaf(h4.w, r3.z, a2);
            }
            float ci = ftanh(a0);
            float ig = fsig(a1);
            float og = fsig(a2);
            c = fmaf(ci, ig, c);
            h = ftanh(c) * og;
            hnext[((j >> 2) * BN + s) * 4 + (j & 3)] = h;
            if (t == myT - 1) d_Hfinal[myb * HN + j] = h;
        }

        // global barrier: publish stores, arrive, spin
        __threadfence();
        __syncthreads();
        if (tid == 0) {
            atomicAdd(&d_ctr, 1u);
            const unsigned tgt = (unsigned)NC * (unsigned)(t + 1);
            while (*((volatile unsigned*)&d_ctr) < tgt) { }
        }
        __syncthreads();
    }
}

// ---------------- final projections: out = (h @ Wp^T + bp) @ Wo^T + bo ----------------
__global__ __launch_bounds__(NTH) void proj_kernel(
    const float* __restrict__ Wp, const float* __restrict__ bp,
    const float* __restrict__ Wo, const float* __restrict__ bo,
    float* __restrict__ out)
{
    __shared__ __align__(16) float hrow[HN];
    __shared__ __align__(16) float tmp[HN];
    const int bidx = blockIdx.x;
    const int tid = threadIdx.x;
    hrow[tid] = d_Hfinal[bidx * HN + tid];
    __syncthreads();
    {
        const float4* wrow = (const float4*)(Wp + tid * HN);
        const float4* hv = (const float4*)hrow;
        float acc = bp[tid];
        #pragma unroll 8
        for (int q = 0; q < HN / 4; q++) {
            float4 w = __ldg(&wrow[q]);
            float4 hh = hv[q];
            acc = fmaf(w.x, hh.x, acc); acc = fmaf(w.y, hh.y, acc);
            acc = fmaf(w.z, hh.z, acc); acc = fmaf(w.w, hh.w, acc);
        }
        tmp[tid] = acc;
    }
    __syncthreads();
    if (tid < 128) {
        const float4* wrow = (const float4*)(Wo + tid * HN);
        const float4* tv = (const float4*)tmp;
        float acc = bo[tid];
        #pragma unroll 8
        for (int q = 0; q < HN / 4; q++) {
            float4 w = __ldg(&wrow[q]);
            float4 tt = tv[q];
            acc = fmaf(w.x, tt.x, acc); acc = fmaf(w.y, tt.y, acc);
            acc = fmaf(w.z, tt.z, acc); acc = fmaf(w.w, tt.w, acc);
        }
        out[bidx * 128 + tid] = acc;
    }
}

#define SMEM_BYTES (19584 * 4 + 2 * BN * 4)

extern "C" void kernel_launch(void* const* d_in, const int* in_sizes, int n_in,
                              void* d_out, int out_size) {
    const float* x    = (const float*)d_in[0];
    const int*   lens = (const int*)d_in[1];
    const float* W    = (const float*)d_in[2];
    const float* R    = (const float*)d_in[3];
    const float* b    = (const float*)d_in[4];
    const float* bt   = (const float*)d_in[5];
    const float* Wp   = (const float*)d_in[6];
    const float* bp   = (const float*)d_in[7];
    const float* Wo   = (const float*)d_in[8];
    const float* bo   = (const float*)d_in[9];
    float* out = (float*)d_out;

    cudaFuncSetAttribute(lstm_kernel, cudaFuncAttributeMaxDynamicSharedMemorySize, SMEM_BYTES);

    setup_kernel<<<1, NTH>>>(lens);
    lstm_kernel<<<NC, NTH, SMEM_BYTES>>>(x, W, R, b, bt);
    proj_kernel<<<BN, NTH>>>(Wp, bp, Wo, bo, out);
}

// round 2
// speedup vs baseline: 1.6579x; 1.6579x over previous
#include <cuda_runtime.h>
#include <math.h>

#define BN 128
#define LN 2048
#define FN 128
#define HN 256
#define G3 768
#define NTICK 5
#define TMX (LN + NTICK)
#define NC 128
#define NTH 256

// Scratch (module-scope device memory; no runtime allocation)
__device__ float d_Hbuf[2][HN * BN];   // ping-pong h, layout [k][s] (s contiguous)
__device__ float d_Hfinal[BN * HN];    // final h per ORIGINAL batch index, [b][j]
__device__ int d_perm[BN];             // sorted (desc by len) slot -> original batch
__device__ int d_slen[BN];             // sorted lens
__device__ int d_ns[TMX];              // #batches with len > t
__device__ int d_maxT;
__device__ unsigned d_ctr;             // global barrier counter

// ---------------- setup: sort batches, reset state (every launch) ----------------
__global__ __launch_bounds__(NTH) void setup_kernel(const int* __restrict__ lens) {
    __shared__ int sl[BN];
    int tid = threadIdx.x;
    if (tid < BN) sl[tid] = lens[tid];
    __syncthreads();
    if (tid < BN) {
        int ml = sl[tid];
        int r = 0;
        for (int i = 0; i < BN; i++) {
            int li = sl[i];
            if (li > ml || (li == ml && i < tid)) r++;
        }
        d_perm[r] = tid;
        d_slen[r] = ml;
    }
    if (tid == 0) {
        int mx = 0;
        for (int i = 0; i < BN; i++) mx = (sl[i] > mx) ? sl[i] : mx;
        d_maxT = mx + NTICK;
        d_ctr = 0u;
    }
    for (int t = tid; t < TMX; t += NTH) {
        int c = 0;
        for (int i = 0; i < BN; i++) c += (sl[i] > t) ? 1 : 0;
        d_ns[t] = c;
    }
    float* hb = &d_Hbuf[0][0];
    for (int i = tid; i < 2 * HN * BN; i += NTH) hb[i] = 0.f;
}

// ---------------- activations (fast, ~1e-7 abs err) ----------------
__device__ __forceinline__ float fclamp15(float v) {
    return fminf(fmaxf(v, -15.f), 15.f);
}
__device__ __forceinline__ float ftanh(float v) {
    float e = __expf(2.f * fclamp15(v));
    return __fdividef(e - 1.f, e + 1.f);
}
__device__ __forceinline__ float fsig(float v) {
    return __fdividef(1.f, 1.f + __expf(-fclamp15(v)));
}

// smem layout (floats)
#define SM_RS   0            // 256*12 = 3072
#define SM_WS   3072         // 128*12 = 1536
#define SM_XS   4608         // 128*132 = 16896
#define SM_INT  21504        // sperm[128], slen[128] (ints)
#define SMEM_BYTES (21504 * 4 + 2 * BN * 4)

// ---------------- persistent lockstep LSTM + fused projections ----------------
// 128 CTAs x 256 threads. CTA bx owns hidden dims {2bx, 2bx+1} (6 gate columns).
// Thread = (bg = tid>>3 in [0,32), ks = tid&7): 4 batches (4bg..4bg+3) x 2 dims x 3 gates,
// k-split 8 ways interleaved (k = 8i + ks), reduced via shfl.bfly over ks bits.
__global__ __launch_bounds__(NTH, 1) void lstm_kernel(
    const float* __restrict__ x, const float* __restrict__ W,
    const float* __restrict__ R, const float* __restrict__ b,
    const float* __restrict__ bt,
    const float* __restrict__ Wp, const float* __restrict__ bp,
    const float* __restrict__ Wo, const float* __restrict__ bo,
    float* __restrict__ out)
{
    extern __shared__ float sm[];
    float* Rs = sm + SM_RS;                 // [k][12]: d*4+g
    float* Ws = sm + SM_WS;                 // [k][12]
    float* xs = sm + SM_XS;                 // [k][132] (s contiguous, stride 132)
    int* sperm = (int*)(sm + SM_INT);       // [BN]
    int* slen  = sperm + BN;                // [BN]

    const int tid = threadIdx.x;
    const int bx  = blockIdx.x;
    const int ks  = tid & 7;
    const int bg  = tid >> 3;

    const float4* Rs4 = (const float4*)Rs;
    const float4* Ws4 = (const float4*)Ws;
    const float4* xs4 = (const float4*)xs;

    // load weight slices: Rs[k*12 + d*4 + g] = R[k][g*HN + 2bx+d]
    for (int i = tid; i < HN * 6; i += NTH) {
        int k = i / 6, rem = i % 6, dd = rem / 3, g = rem % 3;
        Rs[k * 12 + dd * 4 + g] = __ldg(&R[k * G3 + g * HN + ((bx << 1) + dd)]);
    }
    for (int i = tid; i < FN * 6; i += NTH) {
        int k = i / 6, rem = i % 6, dd = rem / 3, g = rem % 3;
        Ws[k * 12 + dd * 4 + g] = __ldg(&W[k * G3 + g * HN + ((bx << 1) + dd)]);
    }
    if (tid < BN) { sperm[tid] = d_perm[tid]; slen[tid] = d_slen[tid]; }
    __syncthreads();

    // per-lane ownership after reduction
    const int down = ks >> 2;
    const int sown = (bg << 2) + (((ks >> 1) & 1) << 1) + (ks & 1);
    const int jown = (bx << 1) + down;
    const int mylen = slen[sown];
    const int myb   = sperm[sown];
    const int myT   = mylen + NTICK;
    const int warpMaxT = slen[(tid >> 5) << 4] + NTICK;  // warp covers batches [16w,16w+16)
    const float b0c = __ldg(&b[jown]),      b1c = __ldg(&b[jown + HN]),      b2c = __ldg(&b[jown + 2 * HN]);
    const float t0c = __ldg(&bt[jown]),     t1c = __ldg(&bt[jown + HN]),     t2c = __ldg(&bt[jown + 2 * HN]);
    const int maxT = d_maxT;

    float c = 0.f, h = 0.f;

    for (int t = 0; t < maxT; t++) {
        // ---- stage x_t as [k][s], conflict-free stores (banks = s2) ----
        const int ns = (t < LN) ? __ldg(&d_ns[t]) : 0;
        for (int base = 0; base < ns; base += 32) {
            for (int it = tid; it < 1024; it += NTH) {
                int s2 = base + (it & 31);
                int kq = it >> 5;
                float4 v = make_float4(0.f, 0.f, 0.f, 0.f);
                if (s2 < ns)
                    v = __ldg((const float4*)(x + (size_t)sperm[s2] * (LN * FN)
                                                + (size_t)t * FN + (kq << 2)));
                int kb = kq << 2;
                xs[(kb + 0) * 132 + s2] = v.x;
                xs[(kb + 1) * 132 + s2] = v.y;
                xs[(kb + 2) * 132 + s2] = v.z;
                xs[(kb + 3) * 132 + s2] = v.w;
            }
        }
        __syncthreads();

        if (t <= warpMaxT) {
            float a[4][6];
            #pragma unroll
            for (int ii = 0; ii < 4; ii++)
                #pragma unroll
                for (int g = 0; g < 6; g++) a[ii][g] = 0.f;

            // ---- recurrent part: h from L2 ping buffer ----
            const float4* Hp = (const float4*)(&d_Hbuf[t & 1][0]);
            #pragma unroll 4
            for (int i = 0; i < 32; i++) {
                const int k = (i << 3) + ks;
                float4 h4 = __ldcg(Hp + (k << 5) + bg);
                float4 w0 = Rs4[k * 3 + 0];
                float4 w1 = Rs4[k * 3 + 1];
                a[0][0] = fmaf(h4.x, w0.x, a[0][0]); a[0][1] = fmaf(h4.x, w0.y, a[0][1]); a[0][2] = fmaf(h4.x, w0.z, a[0][2]);
                a[0][3] = fmaf(h4.x, w1.x, a[0][3]); a[0][4] = fmaf(h4.x, w1.y, a[0][4]); a[0][5] = fmaf(h4.x, w1.z, a[0][5]);
                a[1][0] = fmaf(h4.y, w0.x, a[1][0]); a[1][1] = fmaf(h4.y, w0.y, a[1][1]); a[1][2] = fmaf(h4.y, w0.z, a[1][2]);
                a[1][3] = fmaf(h4.y, w1.x, a[1][3]); a[1][4] = fmaf(h4.y, w1.y, a[1][4]); a[1][5] = fmaf(h4.y, w1.z, a[1][5]);
                a[2][0] = fmaf(h4.z, w0.x, a[2][0]); a[2][1] = fmaf(h4.z, w0.y, a[2][1]); a[2][2] = fmaf(h4.z, w0.z, a[2][2]);
                a[2][3] = fmaf(h4.z, w1.x, a[2][3]); a[2][4] = fmaf(h4.z, w1.y, a[2][4]); a[2][5] = fmaf(h4.z, w1.z, a[2][5]);
                a[3][0] = fmaf(h4.w, w0.x, a[3][0]); a[3][1] = fmaf(h4.w, w0.y, a[3][1]); a[3][2] = fmaf(h4.w, w0.z, a[3][2]);
                a[3][3] = fmaf(h4.w, w1.x, a[3][3]); a[3][4] = fmaf(h4.w, w1.y, a[3][4]); a[3][5] = fmaf(h4.w, w1.z, a[3][5]);
            }

            // ---- input part (skip groups fully past ns; staged zeros mask partials) ----
            if ((bg << 2) < ns) {
                #pragma unroll 4
                for (int i = 0; i < 16; i++) {
                    const int k = (i << 3) + ks;
                    float4 x4 = xs4[k * 33 + bg];
                    float4 w0 = Ws4[k * 3 + 0];
                    float4 w1 = Ws4[k * 3 + 1];
                    a[0][0] = fmaf(x4.x, w0.x, a[0][0]); a[0][1] = fmaf(x4.x, w0.y, a[0][1]); a[0][2] = fmaf(x4.x, w0.z, a[0][2]);
                    a[0][3] = fmaf(x4.x, w1.x, a[0][3]); a[0][4] = fmaf(x4.x, w1.y, a[0][4]); a[0][5] = fmaf(x4.x, w1.z, a[0][5]);
                    a[1][0] = fmaf(x4.y, w0.x, a[1][0]); a[1][1] = fmaf(x4.y, w0.y, a[1][1]); a[1][2] = fmaf(x4.y, w0.z, a[1][2]);
                    a[1][3] = fmaf(x4.y, w1.x, a[1][3]); a[1][4] = fmaf(x4.y, w1.y, a[1][4]); a[1][5] = fmaf(x4.y, w1.z, a[1][5]);
                    a[2][0] = fmaf(x4.z, w0.x, a[2][0]); a[2][1] = fmaf(x4.z, w0.y, a[2][1]); a[2][2] = fmaf(x4.z, w0.z, a[2][2]);
                    a[2][3] = fmaf(x4.z, w1.x, a[2][3]); a[2][4] = fmaf(x4.z, w1.y, a[2][4]); a[2][5] = fmaf(x4.z, w1.z, a[2][5]);
                    a[3][0] = fmaf(x4.w, w0.x, a[3][0]); a[3][1] = fmaf(x4.w, w0.y, a[3][1]); a[3][2] = fmaf(x4.w, w0.z, a[3][2]);
                    a[3][3] = fmaf(x4.w, w1.x, a[3][3]); a[3][4] = fmaf(x4.w, w1.y, a[3][4]); a[3][5] = fmaf(x4.w, w1.z, a[3][5]);
                }
            }

            // ---- bfly reduction over ks bits, progressively shedding values ----
            float r12[4][3];
            {
                const bool hi = (ks & 4) != 0;
                #pragma unroll
                for (int ii = 0; ii < 4; ii++)
                    #pragma unroll
                    for (int g = 0; g < 3; g++) {
                        float send = hi ? a[ii][g] : a[ii][3 + g];
                        float recv = __shfl_xor_sync(0xffffffffu, send, 4);
                        float keep = hi ? a[ii][3 + g] : a[ii][g];
                        r12[ii][g] = keep + recv;
                    }
            }
            float r6[2][3];
            {
                const bool hi = (ks & 2) != 0;
                #pragma unroll
                for (int p = 0; p < 2; p++)
                    #pragma unroll
                    for (int g = 0; g < 3; g++) {
                        float send = hi ? r12[p][g] : r12[2 + p][g];
                        float recv = __shfl_xor_sync(0xffffffffu, send, 2);
                        float keep = hi ? r12[2 + p][g] : r12[p][g];
                        r6[p][g] = keep + recv;
                    }
            }
            float pre[3];
            {
                const bool hi = (ks & 1) != 0;
                #pragma unroll
                for (int g = 0; g < 3; g++) {
                    float send = hi ? r6[0][g] : r6[1][g];
                    float recv = __shfl_xor_sync(0xffffffffu, send, 1);
                    float keep = hi ? r6[1][g] : r6[0][g];
                    pre[g] = keep + recv;
                }
            }

            // ---- cell update for owned (sown, jown) ----
            if (t < myT) {
                float p0 = pre[0] + b0c, p1 = pre[1] + b1c, p2 = pre[2] + b2c;
                if (t >= mylen) { p0 += t0c; p1 += t1c; p2 += t2c; }
                c = fmaf(ftanh(p0), fsig(p1), c);
                h = ftanh(c) * fsig(p2);
                if (t == myT - 1) d_Hfinal[myb * HN + jown] = h;
            }
            d_Hbuf[(t + 1) & 1][jown * BN + sown] = h;
        }

        // ---- global lockstep barrier ----
        __threadfence();
        __syncthreads();
        if (tid == 0) {
            atomicAdd(&d_ctr, 1u);
            const unsigned tgt = (unsigned)NC * (unsigned)(t + 1);
            while (*((volatile unsigned*)&d_ctr) < tgt) { }
        }
        __syncthreads();
    }

    // ---- fused projections: CTA bx handles batch bx ----
    float* hrow = xs;        // reuse
    float* tmp  = xs + 256;
    hrow[tid] = __ldcg(&d_Hfinal[bx * HN + tid]);
    __syncthreads();
    {
        const float4* wrow = (const float4*)(Wp + tid * HN);
        const float4* hv = (const float4*)hrow;
        float acc = __ldg(&bp[tid]);
        #pragma unroll 8
        for (int q = 0; q < HN / 4; q++) {
            float4 w = __ldg(&wrow[q]);
            float4 hh = hv[q];
            acc = fmaf(w.x, hh.x, acc); acc = fmaf(w.y, hh.y, acc);
            acc = fmaf(w.z, hh.z, acc); acc = fmaf(w.w, hh.w, acc);
        }
        tmp[tid] = acc;
    }
    __syncthreads();
    if (tid < 128) {
        const float4* wrow = (const float4*)(Wo + tid * HN);
        const float4* tv = (const float4*)tmp;
        float acc = __ldg(&bo[tid]);
        #pragma unroll 8
        for (int q = 0; q < HN / 4; q++) {
            float4 w = __ldg(&wrow[q]);
            float4 tt = tv[q];
            acc = fmaf(w.x, tt.x, acc); acc = fmaf(w.y, tt.y, acc);
            acc = fmaf(w.z, tt.z, acc); acc = fmaf(w.w, tt.w, acc);
        }
        out[bx * 128 + tid] = acc;
    }
}

extern "C" void kernel_launch(void* const* d_in, const int* in_sizes, int n_in,
                              void* d_out, int out_size) {
    const float* x    = (const float*)d_in[0];
    const int*   lens = (const int*)d_in[1];
    const float* W    = (const float*)d_in[2];
    const float* R    = (const float*)d_in[3];
    const float* b    = (const float*)d_in[4];
    const float* bt   = (const float*)d_in[5];
    const float* Wp   = (const float*)d_in[6];
    const float* bp   = (const float*)d_in[7];
    const float* Wo   = (const float*)d_in[8];
    const float* bo   = (const float*)d_in[9];
    float* out = (float*)d_out;

    cudaFuncSetAttribute(lstm_kernel, cudaFuncAttributeMaxDynamicSharedMemorySize, SMEM_BYTES);

    setup_kernel<<<1, NTH>>>(lens);
    lstm_kernel<<<NC, NTH, SMEM_BYTES>>>(x, W, R, b, bt, Wp, bp, Wo, bo, out);
}

// round 3
// speedup vs baseline: 3.9161x; 2.3621x over previous
#include <cuda_runtime.h>
#include <math.h>

#define BN 128
#define LN 2048
#define FN 128
#define HN 256
#define G3 768
#define NTICK 5
#define NC 128
#define NTH 256
#define NBG 8      // batch groups (16 batches each)
#define NDG 16     // dim groups (16 dims each)

// Scratch (module-scope device memory; no runtime allocation)
// h ping-pong: [buf][bj][k(256)][s(16)] -> each batch-group's block is 16KB contiguous
__device__ float d_Hbuf[2][NBG * HN * 16];
__device__ float d_Hfinal[BN * HN];    // final h per ORIGINAL batch, [b][j]
__device__ int d_perm[BN];             // sorted (desc by len) rank -> original batch
__device__ int d_slen[BN];             // sorted lens
__device__ int d_maxT;
__device__ unsigned d_ctr;             // global barrier counter

// ---------------- setup: sort batches, reset state (every launch) ----------------
__global__ __launch_bounds__(NTH) void setup_kernel(const int* __restrict__ lens) {
    __shared__ int sl[BN];
    int tid = threadIdx.x;
    if (tid < BN) sl[tid] = lens[tid];
    __syncthreads();
    if (tid < BN) {
        int ml = sl[tid];
        int r = 0;
        for (int i = 0; i < BN; i++) {
            int li = sl[i];
            if (li > ml || (li == ml && i < tid)) r++;
        }
        d_perm[r] = tid;
        d_slen[r] = ml;
    }
    if (tid == 0) {
        int mx = 0;
        for (int i = 0; i < BN; i++) mx = (sl[i] > mx) ? sl[i] : mx;
        d_maxT = mx + NTICK;
        d_ctr = 0u;
    }
    float* hb = &d_Hbuf[0][0];
    for (int i = tid; i < NBG * HN * 16; i += NTH) hb[i] = 0.f;
}

// ---------------- activations ----------------
__device__ __forceinline__ float fclamp15(float v) { return fminf(fmaxf(v, -15.f), 15.f); }
__device__ __forceinline__ float ftanh(float v) {
    float e = __expf(2.f * fclamp15(v));
    return __fdividef(e - 1.f, e + 1.f);
}
__device__ __forceinline__ float fsig(float v) {
    return __fdividef(1.f, 1.f + __expf(-fclamp15(v)));
}

// smem layout (floats)
#define SM_RS   0                       // 256*68 = 17408
#define SM_WS   17408                   // 128*68 = 8704
#define SM_HS   26112                   // 256*20 = 5120
#define SM_XS   31232                   // 128*20 = 2560
#define SM_INT  33792                   // sperm[128], slen[128]
#define SM_FLOATS 34048
#define SMEM_BYTES (SM_FLOATS * 4 + 64)

// ---------------- persistent lockstep LSTM + fused projections ----------------
// 128 CTAs = (di 0..16) x (bj 0..8); CTA computes dims [16di,16di+16) x batches [16bj,16bj+16).
// Thread tid: ks = tid&15 (k-split), dg = (tid>>4)&7 (dim pair), sg = tid>>7 (batch octet).
// Accums: a[8 batches][2 dims * 3 gates]; k = 16*i + ks; 4-round bfly reduction over ks.
__global__ __launch_bounds__(NTH, 1) void lstm_kernel(
    const float* __restrict__ x, const float* __restrict__ W,
    const float* __restrict__ R, const float* __restrict__ b,
    const float* __restrict__ bt,
    const float* __restrict__ Wp, const float* __restrict__ bp,
    const float* __restrict__ Wo, const float* __restrict__ bo,
    float* __restrict__ out)
{
    extern __shared__ float sm[];
    float* Rs = sm + SM_RS;            // [k][8 dg][8: d0g0,d0g1,d0g2,_,d1g0,d1g1,d1g2,_]
    float* Ws = sm + SM_WS;            // [k][8 dg][8]
    float* hs = sm + SM_HS;            // [k][20] (16 batches used)
    float* xs = sm + SM_XS;            // [k][20]
    int* sperm = (int*)(sm + SM_INT);
    int* slen  = sperm + BN;

    const int tid = threadIdx.x;
    const int bx  = blockIdx.x;
    const int di  = bx >> 3;
    const int bj  = bx & 7;
    const int ks  = tid & 15;
    const int dg  = (tid >> 4) & 7;
    const int sg  = tid >> 7;

    const float4* Rs4 = (const float4*)Rs;
    const float4* Ws4 = (const float4*)Ws;
    const float4* hs4 = (const float4*)hs;
    const float4* xs4 = (const float4*)xs;

    // ---- load weight slices ----
    for (int i = tid; i < HN * 68; i += NTH) {
        int k = i / 68, cr = i % 68;
        float v = 0.f;
        if (cr < 64) {
            int dgl = cr >> 3, e = cr & 7;
            int d = e >> 2, g = e & 3;
            if (g < 3) v = __ldg(&R[k * G3 + g * HN + (di << 4) + (dgl << 1) + d]);
        }
        Rs[i] = v;
    }
    for (int i = tid; i < FN * 68; i += NTH) {
        int k = i / 68, cr = i % 68;
        float v = 0.f;
        if (cr < 64) {
            int dgl = cr >> 3, e = cr & 7;
            int d = e >> 2, g = e & 3;
            if (g < 3) v = __ldg(&W[k * G3 + g * HN + (di << 4) + (dgl << 1) + d]);
        }
        Ws[i] = v;
    }
    if (tid < BN) { sperm[tid] = d_perm[tid]; slen[tid] = d_slen[tid]; }
    __syncthreads();

    // ownership after reduction
    const int down  = ks >> 3;
    const int sown  = (sg << 3) + (ks & 7);          // local batch 0..15
    const int jloc  = (dg << 1) + down;              // local dim 0..15
    const int jglob = (di << 4) + jloc;
    const int rank  = (bj << 4) + sown;
    const int mylen = slen[rank];
    const int myb   = sperm[rank];
    const int myT   = mylen + NTICK;
    const int sgMaxLen = slen[(bj << 4) + (sg << 3)]; // sorted desc -> first of octet is max
    const int warpEnd  = sgMaxLen + NTICK;
    const int gMaxLen  = slen[bj << 4];
    const int gMaxT    = gMaxLen + NTICK;
    const float b0c = __ldg(&b[jglob]),  b1c = __ldg(&b[jglob + HN]),  b2c = __ldg(&b[jglob + 2 * HN]);
    const float t0c = __ldg(&bt[jglob]), t1c = __ldg(&bt[jglob + HN]), t2c = __ldg(&bt[jglob + 2 * HN]);
    const int maxT = d_maxT;

    float c = 0.f, h = 0.f;

    for (int t = 0; t < maxT; t++) {
        if (t < gMaxT) {
            // ---- stage h tile [256k][16s] (16KB contiguous in L2) ----
            const float4* Hg4 = (const float4*)(&d_Hbuf[t & 1][bj << 12]);
            float4* hs4w = (float4*)hs;
            #pragma unroll
            for (int r = 0; r < 4; r++) {
                int f = tid + (r << 8);           // 0..1024 float4s
                float4 v = __ldcg(Hg4 + f);
                hs4w[(f >> 2) * 5 + (f & 3)] = v;
            }
            // ---- stage x tile [128k][16s] with per-batch masking ----
            if (t < gMaxLen) {
                #pragma unroll
                for (int r = 0; r < 2; r++) {
                    int f = tid + (r << 8);       // 0..512 float4s
                    int s = f & 15, kq = f >> 4;
                    int rk = (bj << 4) + s;
                    float4 v = make_float4(0.f, 0.f, 0.f, 0.f);
                    if (t < slen[rk])
                        v = __ldg((const float4*)(x + (size_t)sperm[rk] * (LN * FN)
                                                    + (size_t)t * FN) + kq);
                    int kb = kq << 2;
                    xs[(kb + 0) * 20 + s] = v.x;
                    xs[(kb + 1) * 20 + s] = v.y;
                    xs[(kb + 2) * 20 + s] = v.z;
                    xs[(kb + 3) * 20 + s] = v.w;
                }
            }
        }
        __syncthreads();

        if (t < warpEnd) {
            float a[8][6];
            #pragma unroll
            for (int si = 0; si < 8; si++)
                #pragma unroll
                for (int g = 0; g < 6; g++) a[si][g] = 0.f;

#define FMA6(si, hv) \
    a[si][0] = fmaf(hv, w0.x, a[si][0]); a[si][1] = fmaf(hv, w0.y, a[si][1]); a[si][2] = fmaf(hv, w0.z, a[si][2]); \
    a[si][3] = fmaf(hv, w1.x, a[si][3]); a[si][4] = fmaf(hv, w1.y, a[si][4]); a[si][5] = fmaf(hv, w1.z, a[si][5]);

            // ---- recurrent part: 16 iters x 48 FMA ----
            #pragma unroll 4
            for (int i = 0; i < 16; i++) {
                const int k = (i << 4) + ks;
                float4 ha = hs4[k * 5 + (sg << 1)];
                float4 hb = hs4[k * 5 + (sg << 1) + 1];
                float4 w0 = Rs4[k * 17 + (dg << 1)];
                float4 w1 = Rs4[k * 17 + (dg << 1) + 1];
                FMA6(0, ha.x) FMA6(1, ha.y) FMA6(2, ha.z) FMA6(3, ha.w)
                FMA6(4, hb.x) FMA6(5, hb.y) FMA6(6, hb.z) FMA6(7, hb.w)
            }
            // ---- input part (staged zeros mask inactive batches) ----
            if (t < sgMaxLen) {
                #pragma unroll 4
                for (int i = 0; i < 8; i++) {
                    const int k = (i << 4) + ks;
                    float4 ha = xs4[k * 5 + (sg << 1)];
                    float4 hb = xs4[k * 5 + (sg << 1) + 1];
                    float4 w0 = Ws4[k * 17 + (dg << 1)];
                    float4 w1 = Ws4[k * 17 + (dg << 1) + 1];
                    FMA6(0, ha.x) FMA6(1, ha.y) FMA6(2, ha.z) FMA6(3, ha.w)
                    FMA6(4, hb.x) FMA6(5, hb.y) FMA6(6, hb.z) FMA6(7, hb.w)
                }
            }
#undef FMA6

            // ---- 4-round shedding butterfly over ks bits (warp-local; sg is warp-uniform) ----
            float b24[8][3];
            {
                const bool hid = (ks & 8) != 0;   // my kept d = bit3
                #pragma unroll
                for (int si = 0; si < 8; si++)
                    #pragma unroll
                    for (int g = 0; g < 3; g++) {
                        float send = hid ? a[si][g] : a[si][3 + g];
                        float recv = __shfl_xor_sync(0xffffffffu, send, 8);
                        float keep = hid ? a[si][3 + g] : a[si][g];
                        b24[si][g] = keep + recv;
                    }
            }
            float r12[4][3];
            {
                const bool hb2 = (ks & 4) != 0;
                #pragma unroll
                for (int si = 0; si < 4; si++)
                    #pragma unroll
                    for (int g = 0; g < 3; g++) {
                        float send = hb2 ? b24[si][g] : b24[4 + si][g];
                        float recv = __shfl_xor_sync(0xffffffffu, send, 4);
                        float keep = hb2 ? b24[4 + si][g] : b24[si][g];
                        r12[si][g] = keep + recv;
                    }
            }
            float r6[2][3];
            {
                const bool hb1 = (ks & 2) != 0;
                #pragma unroll
                for (int si = 0; si < 2; si++)
                    #pragma unroll
                    for (int g = 0; g < 3; g++) {
                        float send = hb1 ? r12[si][g] : r12[2 + si][g];
                        float recv = __shfl_xor_sync(0xffffffffu, send, 2);
                        float keep = hb1 ? r12[2 + si][g] : r12[si][g];
                        r6[si][g] = keep + recv;
                    }
            }
            float r3[3];
            {
                const bool hb0 = (ks & 1) != 0;
                #pragma unroll
                for (int g = 0; g < 3; g++) {
                    float send = hb0 ? r6[0][g] : r6[1][g];
                    float recv = __shfl_xor_sync(0xffffffffu, send, 1);
                    float keep = hb0 ? r6[1][g] : r6[0][g];
                    r3[g] = keep + recv;
                }
            }

            // ---- cell update for owned (rank, jglob) ----
            if (t < myT) {
                float p0 = r3[0] + b0c, p1 = r3[1] + b1c, p2 = r3[2] + b2c;
                if (t >= mylen) { p0 += t0c; p1 += t1c; p2 += t2c; }
                c = fmaf(ftanh(p0), fsig(p1), c);
                h = ftanh(c) * fsig(p2);
                __stcg(&d_Hbuf[(t + 1) & 1][(bj << 12) + (jglob << 4) + sown], h);
                if (t == myT - 1) d_Hfinal[myb * HN + jglob] = h;
            }
        }

        // ---- global lockstep barrier (release arrive + acquire spin by tid0) ----
        __syncthreads();
        if (tid == 0) {
            asm volatile("red.release.gpu.global.add.u32 [%0], %1;"
                         :: "l"(&d_ctr), "r"(1u) : "memory");
            const unsigned tgt = (unsigned)NC * (unsigned)(t + 1);
            unsigned v;
            do {
                asm volatile("ld.acquire.gpu.global.u32 %0, [%1];"
                             : "=r"(v) : "l"(&d_ctr) : "memory");
            } while (v < tgt);
        }
        __syncthreads();
    }

    // ---- fused projections: CTA bx handles batch bx ----
    float* hrow = hs;
    float* tmp  = hs + 256;
    hrow[tid] = __ldcg(&d_Hfinal[bx * HN + tid]);
    __syncthreads();
    {
        const float4* wrow = (const float4*)(Wp + tid * HN);
        const float4* hv = (const float4*)hrow;
        float acc = __ldg(&bp[tid]);
        #pragma unroll 8
        for (int q = 0; q < HN / 4; q++) {
            float4 w = __ldg(&wrow[q]);
            float4 hh = hv[q];
            acc = fmaf(w.x, hh.x, acc); acc = fmaf(w.y, hh.y, acc);
            acc = fmaf(w.z, hh.z, acc); acc = fmaf(w.w, hh.w, acc);
        }
        tmp[tid] = acc;
    }
    __syncthreads();
    if (tid < 128) {
        const float4* wrow = (const float4*)(Wo + tid * HN);
        const float4* tv = (const float4*)tmp;
        float acc = __ldg(&bo[tid]);
        #pragma unroll 8
        for (int q = 0; q < HN / 4; q++) {
            float4 w = __ldg(&wrow[q]);
            float4 tt = tv[q];
            acc = fmaf(w.x, tt.x, acc); acc = fmaf(w.y, tt.y, acc);
            acc = fmaf(w.z, tt.z, acc); acc = fmaf(w.w, tt.w, acc);
        }
        out[bx * 128 + tid] = acc;
    }
}

extern "C" void kernel_launch(void* const* d_in, const int* in_sizes, int n_in,
                              void* d_out, int out_size) {
    const float* x    = (const float*)d_in[0];
    const int*   lens = (const int*)d_in[1];
    const float* W    = (const float*)d_in[2];
    const float* R    = (const float*)d_in[3];
    const float* b    = (const float*)d_in[4];
    const float* bt   = (const float*)d_in[5];
    const float* Wp   = (const float*)d_in[6];
    const float* bp   = (const float*)d_in[7];
    const float* Wo   = (const float*)d_in[8];
    const float* bo   = (const float*)d_in[9];
    float* out = (float*)d_out;

    cudaFuncSetAttribute(lstm_kernel, cudaFuncAttributeMaxDynamicSharedMemorySize, SMEM_BYTES);

    setup_kernel<<<1, NTH>>>(lens);
    lstm_kernel<<<NC, NTH, SMEM_BYTES>>>(x, W, R, b, bt, Wp, bp, Wo, bo, out);
}